// round 6
// baseline (speedup 1.0000x reference)
#include <cuda_runtime.h>
#include <cstdint>
#include <math.h>

#define BB   64
#define HH   1024
#define ED   1024
#define VV   32000
#define TT   50
#define G4   4096
#define START_INDEX 1

#define BM 64
#define BN 256
#define BK 32
#define THR 256
#define SPLITK 8
#define KC_GATES ((2 * HH) / SPLITK)   // 256

#define SMEM_BYTES (2*BK*64*8 + 2*BK*BN*4)   // As2 double + Bs double = 96KB

typedef unsigned long long ull;

// ---------------- device-resident state (no allocations) ----------------
__device__ float g_h[BB * HH];
__device__ float g_c[BB * HH];
__device__ float g_gp[SPLITK][BB * G4];
__device__ float g_logits[(size_t)BB * VV];
__device__ int   g_last[BB];
__device__ float g_wt_out[(size_t)HH * VV];      // W_out^T : [1024][32000]
__device__ float g_wt_g[(size_t)(2*HH) * G4];    // [W_ih|W_hh]^T : [2048][4096]

// ---------------- init ---------------------------------------------------
__global__ void init_kernel(const float* __restrict__ hidden) {
    int i = blockIdx.x * blockDim.x + threadIdx.x;
    if (i < BB * HH) { g_h[i] = hidden[i]; g_c[i] = 0.0f; }
    if (i < BB) g_last[i] = START_INDEX;
}

// ---------------- transpose: dst[NCOLS][NROWS] = src[NROWS][NCOLS]^T -----
__global__ void transpose_kernel(float* __restrict__ dst,
                                 const float* __restrict__ src,
                                 int NROWS, int NCOLS) {
    __shared__ float tile[32][33];
    int n0 = blockIdx.x * 32;
    int k0 = blockIdx.y * 32;
    int tx = threadIdx.x & 31;
    int ty = threadIdx.x >> 5;       // 0..7
    #pragma unroll
    for (int j = 0; j < 4; j++)
        tile[ty + j * 8][tx] = src[(size_t)(n0 + ty + j * 8) * NCOLS + k0 + tx];
    __syncthreads();
    #pragma unroll
    for (int j = 0; j < 4; j++)
        dst[(size_t)(k0 + ty + j * 8) * NROWS + n0 + tx] = tile[tx][ty + j * 8];
}

// ---------------- packed f32x2 helpers -----------------------------------
__device__ __forceinline__ ull pk2(float x, float y) {
    ull r;
    asm("mov.b64 %0, {%1, %2};" : "=l"(r) : "f"(x), "f"(y));
    return r;
}
__device__ __forceinline__ void ffma2(ull& d, ull a, ull b) {
    asm("fma.rn.f32x2 %0, %1, %2, %0;" : "+l"(d) : "l"(a), "l"(b));
}
union U2 { ull u; float2 f; };

__device__ __forceinline__ void cpa16(unsigned int dst, const float* src) {
    asm volatile("cp.async.cg.shared.global [%0], [%1], 16;\n" :: "r"(dst), "l"(src));
}
__device__ __forceinline__ void cpa_commit() {
    asm volatile("cp.async.commit_group;\n" ::: "memory");
}

// ---------------- GEMM v4: C[64 x N] = A[64 x K] @ Wt[K x N] -------------
// 256 threads (2 warps/SMSP). BM=64, BN=256, BK=32.
// Per-thread: 8 rows (tm = t>>5, warp-uniform -> A LDS broadcasts) x
// 8 cols (tn = t&31: cols tn*4 and 128+tn*4). acc[8][4] ull.
// Per kk per thread: 4 A LDS.128 (broadcast) + 2 B LDS.128 + 32 FFMA2.
// B staged via cp.async from pre-transposed weights; A splatted via LDG+STS.
template<bool CAT>
__global__ void __launch_bounds__(THR) gemm4_kernel(
    const float* __restrict__ emb,
    const float* __restrict__ wt,    // [K][N] transposed weights
    const float* __restrict__ bias,
    float* __restrict__ Cout,
    int N, int Kc)
{
    extern __shared__ char dynsmem[];
    ull*   As2 = (ull*)dynsmem;                       // [2][BK][64]
    float* Bs  = (float*)(dynsmem + 2 * BK * 64 * 8); // [2][BK][BN]

    const int t  = threadIdx.x;
    const int n0 = blockIdx.x * BN;
    const int kbase = CAT ? blockIdx.y * Kc : 0;
    float* C = Cout + (CAT ? (size_t)blockIdx.y * BM * N : 0);

    // ---- A staging mapping: thread t stages row am = t>>2, 8 k-floats
    const int am   = t >> 2;
    const int koff = (t & 3) * 8;
    const float* abase;
    if (CAT) {
        if (kbase < HH) abase = emb + (size_t)g_last[am] * ED + kbase;
        else            abase = g_h + (size_t)am * HH + (kbase - HH);
    } else {
        abase = g_h + (size_t)am * HH;
    }
    abase += koff;

    // ---- compute mapping ----
    const int tn = t & 31;     // col group: cols tn*4 and 128+tn*4
    const int tm = t >> 5;     // row group (0..7): rows tm*8..+7  (warp-uniform)

    ull acc[8][4];
    #pragma unroll
    for (int i = 0; i < 8; i++)
        #pragma unroll
        for (int j = 0; j < 4; j++) acc[i][j] = 0ull;

    const int NT = Kc / BK;

    // ---- helpers ----
    auto stageB = [&](int s, int k0) {
        unsigned int dstBase =
            (unsigned int)__cvta_generic_to_shared(Bs + (size_t)s * BK * BN);
        const float* wsrc = wt + (size_t)(kbase + k0) * N + n0;
        #pragma unroll
        for (int i = 0; i < 8; i++) {
            int seg = t + i * THR;
            int row = seg >> 6;        // 64 segs per k-row (256 floats)
            int cs  = seg & 63;
            cpa16(dstBase + (unsigned int)(row * BN + cs * 4) * 4,
                  wsrc + (size_t)row * N + cs * 4);
        }
        cpa_commit();
    };
    auto stsA = [&](int s, const float4* av) {
        #pragma unroll
        for (int q = 0; q < 2; q++) {
            const float* f = &av[q].x;
            #pragma unroll
            for (int e = 0; e < 4; e++) {
                int k = koff + q * 4 + e;
                As2[((size_t)s * BK + k) * 64 + am] = pk2(f[e], f[e]);
            }
        }
    };

    // ---- prologue: stage tile 0 ----
    {
        float4 av[2];
        av[0] = *(const float4*)(abase + 0);
        av[1] = *(const float4*)(abase + 4);
        stsA(0, av);
        stageB(0, 0);
    }

    float4 avn[2];
    for (int tile = 0; tile < NT; tile++) {
        const int s = tile & 1;
        const bool have = (tile + 1 < NT);
        if (have) {
            stageB(s ^ 1, (tile + 1) * BK);
            const float* ap = abase + (tile + 1) * BK;
            avn[0] = *(const float4*)(ap + 0);
            avn[1] = *(const float4*)(ap + 4);
            asm volatile("cp.async.wait_group 1;\n" ::: "memory");
        } else {
            asm volatile("cp.async.wait_group 0;\n" ::: "memory");
        }
        __syncthreads();

        // ---- compute BK k-steps on buffer s ----
        const ull*   Abuf = As2 + (size_t)s * BK * 64 + tm * 8;
        const float* Bbuf = Bs  + (size_t)s * BK * BN + tn * 4;
        #pragma unroll 8
        for (int kk = 0; kk < BK; kk++) {
            const ull*   ar = Abuf + (size_t)kk * 64;
            const float* br = Bbuf + (size_t)kk * BN;
            ulonglong2 A0 = *(const ulonglong2*)(ar + 0);
            ulonglong2 A1 = *(const ulonglong2*)(ar + 2);
            ulonglong2 A2 = *(const ulonglong2*)(ar + 4);
            ulonglong2 A3 = *(const ulonglong2*)(ar + 6);
            ulonglong2 B0 = *(const ulonglong2*)(br + 0);
            ulonglong2 B1 = *(const ulonglong2*)(br + 128);
#define GROW(i, av) \
            ffma2(acc[i][0], av, B0.x); ffma2(acc[i][1], av, B0.y); \
            ffma2(acc[i][2], av, B1.x); ffma2(acc[i][3], av, B1.y);
            GROW(0, A0.x) GROW(1, A0.y) GROW(2, A1.x) GROW(3, A1.y)
            GROW(4, A2.x) GROW(5, A2.y) GROW(6, A3.x) GROW(7, A3.y)
#undef GROW
        }

        if (have) stsA(s ^ 1, avn);
        __syncthreads();
    }

    // ---- epilogue ----
    float4 bz[2];
    #pragma unroll
    for (int c = 0; c < 2; c++) {
        if (!CAT && bias) bz[c] = *(const float4*)(bias + n0 + c * 128 + tn * 4);
        else              bz[c] = make_float4(0.f, 0.f, 0.f, 0.f);
    }
    #pragma unroll
    for (int i = 0; i < 8; i++) {
        float* crow = C + (size_t)(tm * 8 + i) * N + n0 + tn * 4;
        #pragma unroll
        for (int c = 0; c < 2; c++) {
            U2 lo, hi;
            lo.u = acc[i][2 * c];
            hi.u = acc[i][2 * c + 1];
            float4 v = make_float4(lo.f.x + bz[c].x, lo.f.y + bz[c].y,
                                   hi.f.x + bz[c].z, hi.f.y + bz[c].w);
            *(float4*)(crow + c * 128) = v;
        }
    }
}

// ---------------- LSTM cell: sum split-K partials + elementwise ----------
__global__ void __launch_bounds__(256) cell_kernel(
    const float* __restrict__ b_ih, const float* __restrict__ b_hh)
{
    int idx4 = blockIdx.x * blockDim.x + threadIdx.x;
    if (idx4 >= BB * HH / 4) return;
    int b = idx4 >> 8;
    int n = (idx4 & 255) * 4;

    float4 gq[4];
    #pragma unroll
    for (int q = 0; q < 4; q++) {
        float4 s = make_float4(0.f, 0.f, 0.f, 0.f);
        size_t off = (size_t)b * G4 + q * HH + n;
        #pragma unroll
        for (int p = 0; p < SPLITK; p++) {
            float4 v = *(const float4*)(&g_gp[p][off]);
            s.x += v.x; s.y += v.y; s.z += v.z; s.w += v.w;
        }
        float4 bi = *(const float4*)(b_ih + q * HH + n);
        float4 bh = *(const float4*)(b_hh + q * HH + n);
        s.x += bi.x + bh.x; s.y += bi.y + bh.y;
        s.z += bi.z + bh.z; s.w += bi.w + bh.w;
        gq[q] = s;
    }

    float4 c = *(const float4*)(&g_c[(size_t)b * HH + n]);
    float4 cn, hn;
    #pragma unroll
    for (int e = 0; e < 4; e++) {
        float ig = (&gq[0].x)[e];
        float fg = (&gq[1].x)[e];
        float gg = (&gq[2].x)[e];
        float og = (&gq[3].x)[e];
        float cv = (&c.x)[e];
        float si = 1.0f / (1.0f + expf(-ig));
        float sf = 1.0f / (1.0f + expf(-fg));
        float so = 1.0f / (1.0f + expf(-og));
        float cnew = sf * cv + si * tanhf(gg);
        (&cn.x)[e] = cnew;
        (&hn.x)[e] = so * tanhf(cnew);
    }
    *(float4*)(&g_c[(size_t)b * HH + n]) = cn;
    *(float4*)(&g_h[(size_t)b * HH + n]) = hn;
}

// ---------------- softmax + first-index argmax + output write ------------
__global__ void __launch_bounds__(1024) softmax_kernel(float* __restrict__ out, int t)
{
    const int b   = blockIdx.x;
    const int tid = threadIdx.x;
    const float4* lrow4 = (const float4*)(g_logits + (size_t)b * VV);
    const int NV4 = VV / 4;

    __shared__ float smax[1024];
    __shared__ int   sidx[1024];
    __shared__ float ssum[1024];

    float mx = -3.4e38f;
    int   mi = 0;
    for (int v = tid; v < NV4; v += 1024) {
        float4 l = lrow4[v];
        #pragma unroll
        for (int e = 0; e < 4; e++) {
            float le = (&l.x)[e];
            if (le > mx) { mx = le; mi = v * 4 + e; }
        }
    }
    smax[tid] = mx; sidx[tid] = mi;
    __syncthreads();
    for (int s = 512; s > 0; s >>= 1) {
        if (tid < s) {
            float om = smax[tid + s]; int oi = sidx[tid + s];
            if (om > smax[tid] || (om == smax[tid] && oi < sidx[tid])) {
                smax[tid] = om; sidx[tid] = oi;
            }
        }
        __syncthreads();
    }
    const float rowmax = smax[0];
    const int   pred   = sidx[0];

    float acc = 0.0f;
    for (int v = tid; v < NV4; v += 1024) {
        float4 l = lrow4[v];
        acc += __expf(l.x - rowmax) + __expf(l.y - rowmax)
             + __expf(l.z - rowmax) + __expf(l.w - rowmax);
    }
    ssum[tid] = acc;
    __syncthreads();
    for (int s = 512; s > 0; s >>= 1) {
        if (tid < s) ssum[tid] += ssum[tid + s];
        __syncthreads();
    }
    const float inv = 1.0f / ssum[0];

    float4* orow4 = (float4*)(out + ((size_t)b * TT + t) * VV);
    for (int v = tid; v < NV4; v += 1024) {
        float4 l = lrow4[v];
        float4 o;
        o.x = __expf(l.x - rowmax) * inv;
        o.y = __expf(l.y - rowmax) * inv;
        o.z = __expf(l.z - rowmax) * inv;
        o.w = __expf(l.w - rowmax) * inv;
        orow4[v] = o;
    }

    if (tid == 0) {
        g_last[b] = pred;
        out[(size_t)BB * TT * VV + (size_t)b * TT + t] = (float)pred;
    }
}

// ---------------- launch --------------------------------------------------
extern "C" void kernel_launch(void* const* d_in, const int* in_sizes, int n_in,
                              void* d_out, int out_size) {
    const float* hidden    = (const float*)d_in[0];
    const float* embedding = (const float*)d_in[1];
    const float* W_ih      = (const float*)d_in[2];
    const float* W_hh      = (const float*)d_in[3];
    const float* b_ih      = (const float*)d_in[4];
    const float* b_hh      = (const float*)d_in[5];
    const float* W_out     = (const float*)d_in[6];
    const float* b_out     = (const float*)d_in[7];
    float* out = (float*)d_out;

    float *pgp, *plog, *pwtout, *pwtg;
    cudaGetSymbolAddress((void**)&pgp,    g_gp);
    cudaGetSymbolAddress((void**)&plog,   g_logits);
    cudaGetSymbolAddress((void**)&pwtout, g_wt_out);
    cudaGetSymbolAddress((void**)&pwtg,   g_wt_g);

    // host-side attribute setup — not a graph node
    cudaFuncSetAttribute(gemm4_kernel<true>,
                         cudaFuncAttributeMaxDynamicSharedMemorySize, SMEM_BYTES);
    cudaFuncSetAttribute(gemm4_kernel<false>,
                         cudaFuncAttributeMaxDynamicSharedMemorySize, SMEM_BYTES);

    // pre-transpose weights (once per graph replay, ~50us amortized)
    transpose_kernel<<<dim3(VV / 32, HH / 32), 256>>>(pwtout, W_out, VV, HH);
    transpose_kernel<<<dim3(G4 / 32, HH / 32), 256>>>(pwtg, W_ih, G4, HH);
    transpose_kernel<<<dim3(G4 / 32, HH / 32), 256>>>(
        pwtg + (size_t)HH * G4, W_hh, G4, HH);

    init_kernel<<<(BB * HH + 255) / 256, 256>>>(hidden);

    for (int t = 0; t < TT; t++) {
        // gates: split-K over 8 chunks of K=256 from [W_ih|W_hh]^T
        gemm4_kernel<true><<<dim3(G4 / BN, SPLITK), THR, SMEM_BYTES>>>(
            embedding, pwtg, nullptr, pgp, G4, KC_GATES);

        cell_kernel<<<(BB * HH / 4 + 255) / 256, 256>>>(b_ih, b_hh);

        // logits: h @ W_out^T + b_out  (K=1024)
        gemm4_kernel<false><<<dim3(VV / BN, 1), THR, SMEM_BYTES>>>(
            embedding, pwtout, b_out, plog, VV, HH);

        softmax_kernel<<<BB, 1024>>>(out, t);
    }
}

// round 7
// speedup vs baseline: 1.0779x; 1.0779x over previous
#include <cuda_runtime.h>
#include <cstdint>
#include <math.h>

#define BB   64
#define HH   1024
#define ED   1024
#define VV   32000
#define TT   50
#define G4   4096
#define START_INDEX 1

#define BM 64
#define BN 256
#define BK 32
#define THR 128
#define SPLITK 8
#define KC_GATES ((2 * HH) / SPLITK)   // 256

#define SMEM_BYTES (2*BK*64*8 + 2*BK*BN*4)   // As2 double + Bs double = 96KB

typedef unsigned long long ull;

// ---------------- device-resident state (no allocations) ----------------
__device__ float g_h[BB * HH];
__device__ float g_c[BB * HH];
__device__ float g_gp[SPLITK][BB * G4];
__device__ float g_logits[(size_t)BB * VV];
__device__ int   g_last[BB];
__device__ float g_wt_out[(size_t)HH * VV];      // W_out^T : [1024][32000]
__device__ float g_wt_g[(size_t)(2*HH) * G4];    // [W_ih|W_hh]^T : [2048][4096]

// ---------------- init ---------------------------------------------------
__global__ void init_kernel(const float* __restrict__ hidden) {
    int i = blockIdx.x * blockDim.x + threadIdx.x;
    if (i < BB * HH) { g_h[i] = hidden[i]; g_c[i] = 0.0f; }
    if (i < BB) g_last[i] = START_INDEX;
}

// ---------------- transpose: dst[NCOLS][NROWS] = src[NROWS][NCOLS]^T -----
__global__ void transpose_kernel(float* __restrict__ dst,
                                 const float* __restrict__ src,
                                 int NROWS, int NCOLS) {
    __shared__ float tile[32][33];
    int n0 = blockIdx.x * 32;
    int k0 = blockIdx.y * 32;
    int tx = threadIdx.x & 31;
    int ty = threadIdx.x >> 5;       // 0..7
    #pragma unroll
    for (int j = 0; j < 4; j++)
        tile[ty + j * 8][tx] = src[(size_t)(n0 + ty + j * 8) * NCOLS + k0 + tx];
    __syncthreads();
    #pragma unroll
    for (int j = 0; j < 4; j++)
        dst[(size_t)(k0 + ty + j * 8) * NROWS + n0 + tx] = tile[tx][ty + j * 8];
}

// ---------------- packed f32x2 helpers -----------------------------------
__device__ __forceinline__ ull pk2(float x, float y) {
    ull r;
    asm("mov.b64 %0, {%1, %2};" : "=l"(r) : "f"(x), "f"(y));
    return r;
}
__device__ __forceinline__ void ffma2(ull& d, ull a, ull b) {
    asm("fma.rn.f32x2 %0, %1, %2, %0;" : "+l"(d) : "l"(a), "l"(b));
}
union U2 { ull u; float2 f; };

__device__ __forceinline__ void cpa16(unsigned int dst, const float* src) {
    asm volatile("cp.async.cg.shared.global [%0], [%1], 16;\n" :: "r"(dst), "l"(src));
}
__device__ __forceinline__ void cpa_commit() {
    asm volatile("cp.async.commit_group;\n" ::: "memory");
}

// ---------------- GEMM v3 (R5 geometry): C[64 x N] = A[64 x K] @ Wt[K x N]
// 128 threads. BM=64, BN=256, BK=32. Per-thread: 8 rows x 16 cols.
// 8 A-ull x 8 B-ull -> 64 FFMA2 per kk from 8 LDS.128.
template<bool CAT>
__global__ void __launch_bounds__(THR) gemm3_kernel(
    const float* __restrict__ emb,
    const float* __restrict__ wt,    // [K][N] transposed weights
    const float* __restrict__ bias,
    float* __restrict__ Cout,
    int N, int Kc)
{
    extern __shared__ char dynsmem[];
    ull*   As2 = (ull*)dynsmem;                       // [2][BK][64]
    float* Bs  = (float*)(dynsmem + 2 * BK * 64 * 8); // [2][BK][BN]

    const int t  = threadIdx.x;
    const int n0 = blockIdx.x * BN;
    const int kbase = CAT ? blockIdx.y * Kc : 0;
    float* C = Cout + (CAT ? (size_t)blockIdx.y * BM * N : 0);

    // ---- A staging mapping: thread t stages row m = t>>1, k-half (t&1)*16
    const int am   = t >> 1;
    const int koff = (t & 1) * 16;
    const float* abase;
    if (CAT) {
        if (kbase < HH) abase = emb + (size_t)g_last[am] * ED + kbase;
        else            abase = g_h + (size_t)am * HH + (kbase - HH);
    } else {
        abase = g_h + (size_t)am * HH;
    }
    abase += koff;

    // ---- compute mapping ----
    const int tn = t & 15;     // col group
    const int tm = t >> 4;     // row group (0..7), rows tm*8..+7

    ull acc[8][8];
    #pragma unroll
    for (int i = 0; i < 8; i++)
        #pragma unroll
        for (int j = 0; j < 8; j++) acc[i][j] = 0ull;

    const int NT = Kc / BK;

    // ---- helpers as lambdas ----
    auto stageB = [&](int s, int k0) {
        unsigned int dstBase =
            (unsigned int)__cvta_generic_to_shared(Bs + (size_t)s * BK * BN);
        const float* wsrc = wt + (size_t)(kbase + k0) * N + n0;
        #pragma unroll
        for (int i = 0; i < 16; i++) {
            int seg = t + i * THR;
            int row = seg >> 6;        // 64 segs per k-row (256 floats)
            int cs  = seg & 63;
            cpa16(dstBase + (unsigned int)(row * BN + cs * 4) * 4,
                  wsrc + (size_t)row * N + cs * 4);
        }
        cpa_commit();
    };
    auto stsA = [&](int s, const float4* av) {
        #pragma unroll
        for (int q = 0; q < 4; q++) {
            const float* f = &av[q].x;
            #pragma unroll
            for (int e = 0; e < 4; e++) {
                int k = koff + q * 4 + e;
                As2[((size_t)s * BK + k) * 64 + am] = pk2(f[e], f[e]);
            }
        }
    };

    // ---- prologue: stage tile 0 ----
    {
        float4 av[4];
        #pragma unroll
        for (int q = 0; q < 4; q++) av[q] = *(const float4*)(abase + q * 4);
        stsA(0, av);
        stageB(0, 0);
    }

    float4 avn[4];
    for (int tile = 0; tile < NT; tile++) {
        const int s = tile & 1;
        const bool have = (tile + 1 < NT);
        if (have) {
            stageB(s ^ 1, (tile + 1) * BK);
            const float* ap = abase + (tile + 1) * BK;
            #pragma unroll
            for (int q = 0; q < 4; q++) avn[q] = *(const float4*)(ap + q * 4);
            asm volatile("cp.async.wait_group 1;\n" ::: "memory");
        } else {
            asm volatile("cp.async.wait_group 0;\n" ::: "memory");
        }
        __syncthreads();

        // ---- compute BK k-steps on buffer s ----
        const ull*   Abuf = As2 + (size_t)s * BK * 64 + tm * 8;
        const float* Bbuf = Bs  + (size_t)s * BK * BN + tn * 4;
        #pragma unroll 8
        for (int kk = 0; kk < BK; kk++) {
            const ull*   ar = Abuf + (size_t)kk * 64;
            const float* br = Bbuf + (size_t)kk * BN;
            ulonglong2 A0 = *(const ulonglong2*)(ar + 0);
            ulonglong2 A1 = *(const ulonglong2*)(ar + 2);
            ulonglong2 A2 = *(const ulonglong2*)(ar + 4);
            ulonglong2 A3 = *(const ulonglong2*)(ar + 6);
            ulonglong2 B0 = *(const ulonglong2*)(br + 0);
            ulonglong2 B1 = *(const ulonglong2*)(br + 64);
            ulonglong2 B2 = *(const ulonglong2*)(br + 128);
            ulonglong2 B3 = *(const ulonglong2*)(br + 192);
#define GROW(i, av) \
            ffma2(acc[i][0], av, B0.x); ffma2(acc[i][1], av, B0.y); \
            ffma2(acc[i][2], av, B1.x); ffma2(acc[i][3], av, B1.y); \
            ffma2(acc[i][4], av, B2.x); ffma2(acc[i][5], av, B2.y); \
            ffma2(acc[i][6], av, B3.x); ffma2(acc[i][7], av, B3.y);
            GROW(0, A0.x) GROW(1, A0.y) GROW(2, A1.x) GROW(3, A1.y)
            GROW(4, A2.x) GROW(5, A2.y) GROW(6, A3.x) GROW(7, A3.y)
#undef GROW
        }

        if (have) stsA(s ^ 1, avn);
        __syncthreads();
    }

    // ---- epilogue ----
    float4 bz[4];
    #pragma unroll
    for (int c = 0; c < 4; c++) {
        if (!CAT && bias) bz[c] = *(const float4*)(bias + n0 + c * 64 + tn * 4);
        else              bz[c] = make_float4(0.f, 0.f, 0.f, 0.f);
    }
    #pragma unroll
    for (int i = 0; i < 8; i++) {
        float* crow = C + (size_t)(tm * 8 + i) * N + n0 + tn * 4;
        #pragma unroll
        for (int c = 0; c < 4; c++) {
            U2 lo, hi;
            lo.u = acc[i][2 * c];
            hi.u = acc[i][2 * c + 1];
            float4 v = make_float4(lo.f.x + bz[c].x, lo.f.y + bz[c].y,
                                   hi.f.x + bz[c].z, hi.f.y + bz[c].w);
            *(float4*)(crow + c * 64) = v;
        }
    }
}

// ---------------- LSTM cell: sum split-K partials + elementwise ----------
__global__ void __launch_bounds__(256) cell_kernel(
    const float* __restrict__ b_ih, const float* __restrict__ b_hh)
{
    int idx4 = blockIdx.x * blockDim.x + threadIdx.x;
    if (idx4 >= BB * HH / 4) return;
    int b = idx4 >> 8;
    int n = (idx4 & 255) * 4;

    float4 gq[4];
    #pragma unroll
    for (int q = 0; q < 4; q++) {
        float4 s = make_float4(0.f, 0.f, 0.f, 0.f);
        size_t off = (size_t)b * G4 + q * HH + n;
        #pragma unroll
        for (int p = 0; p < SPLITK; p++) {
            float4 v = *(const float4*)(&g_gp[p][off]);
            s.x += v.x; s.y += v.y; s.z += v.z; s.w += v.w;
        }
        float4 bi = *(const float4*)(b_ih + q * HH + n);
        float4 bh = *(const float4*)(b_hh + q * HH + n);
        s.x += bi.x + bh.x; s.y += bi.y + bh.y;
        s.z += bi.z + bh.z; s.w += bi.w + bh.w;
        gq[q] = s;
    }

    float4 c = *(const float4*)(&g_c[(size_t)b * HH + n]);
    float4 cn, hn;
    #pragma unroll
    for (int e = 0; e < 4; e++) {
        float ig = (&gq[0].x)[e];
        float fg = (&gq[1].x)[e];
        float gg = (&gq[2].x)[e];
        float og = (&gq[3].x)[e];
        float cv = (&c.x)[e];
        float si = 1.0f / (1.0f + expf(-ig));
        float sf = 1.0f / (1.0f + expf(-fg));
        float so = 1.0f / (1.0f + expf(-og));
        float cnew = sf * cv + si * tanhf(gg);
        (&cn.x)[e] = cnew;
        (&hn.x)[e] = so * tanhf(cnew);
    }
    *(float4*)(&g_c[(size_t)b * HH + n]) = cn;
    *(float4*)(&g_h[(size_t)b * HH + n]) = hn;
}

// ---------------- softmax: exp cached in out row, then in-place scale ----
__global__ void __launch_bounds__(1024) softmax_kernel(float* __restrict__ out, int t)
{
    const int b   = blockIdx.x;
    const int tid = threadIdx.x;
    const float4* lrow4 = (const float4*)(g_logits + (size_t)b * VV);
    const int NV4 = VV / 4;

    __shared__ float smax[1024];
    __shared__ int   sidx[1024];
    __shared__ float ssum[1024];

    // pass 1: max with first-occurrence index
    float mx = -3.4e38f;
    int   mi = 0;
    for (int v = tid; v < NV4; v += 1024) {
        float4 l = lrow4[v];
        #pragma unroll
        for (int e = 0; e < 4; e++) {
            float le = (&l.x)[e];
            if (le > mx) { mx = le; mi = v * 4 + e; }
        }
    }
    smax[tid] = mx; sidx[tid] = mi;
    __syncthreads();
    for (int s = 512; s > 0; s >>= 1) {
        if (tid < s) {
            float om = smax[tid + s]; int oi = sidx[tid + s];
            if (om > smax[tid] || (om == smax[tid] && oi < sidx[tid])) {
                smax[tid] = om; sidx[tid] = oi;
            }
        }
        __syncthreads();
    }
    const float rowmax = smax[0];
    const int   pred   = sidx[0];

    // pass 2: write unnormalized exp into out row, accumulate sum
    float4* orow4 = (float4*)(out + ((size_t)b * TT + t) * VV);
    float acc = 0.0f;
    for (int v = tid; v < NV4; v += 1024) {
        float4 l = lrow4[v];
        float4 e;
        e.x = __expf(l.x - rowmax);
        e.y = __expf(l.y - rowmax);
        e.z = __expf(l.z - rowmax);
        e.w = __expf(l.w - rowmax);
        orow4[v] = e;
        acc += e.x + e.y + e.z + e.w;
    }
    ssum[tid] = acc;
    __syncthreads();
    for (int s = 512; s > 0; s >>= 1) {
        if (tid < s) ssum[tid] += ssum[tid + s];
        __syncthreads();
    }
    const float inv = 1.0f / ssum[0];

    // pass 3: in-place scale (no exp)
    for (int v = tid; v < NV4; v += 1024) {
        float4 e = orow4[v];
        e.x *= inv; e.y *= inv; e.z *= inv; e.w *= inv;
        orow4[v] = e;
    }

    if (tid == 0) {
        g_last[b] = pred;
        out[(size_t)BB * TT * VV + (size_t)b * TT + t] = (float)pred;
    }
}

// ---------------- launch --------------------------------------------------
extern "C" void kernel_launch(void* const* d_in, const int* in_sizes, int n_in,
                              void* d_out, int out_size) {
    const float* hidden    = (const float*)d_in[0];
    const float* embedding = (const float*)d_in[1];
    const float* W_ih      = (const float*)d_in[2];
    const float* W_hh      = (const float*)d_in[3];
    const float* b_ih      = (const float*)d_in[4];
    const float* b_hh      = (const float*)d_in[5];
    const float* W_out     = (const float*)d_in[6];
    const float* b_out     = (const float*)d_in[7];
    float* out = (float*)d_out;

    float *pgp, *plog, *pwtout, *pwtg;
    cudaGetSymbolAddress((void**)&pgp,    g_gp);
    cudaGetSymbolAddress((void**)&plog,   g_logits);
    cudaGetSymbolAddress((void**)&pwtout, g_wt_out);
    cudaGetSymbolAddress((void**)&pwtg,   g_wt_g);

    // host-side attribute setup — not a graph node
    cudaFuncSetAttribute(gemm3_kernel<true>,
                         cudaFuncAttributeMaxDynamicSharedMemorySize, SMEM_BYTES);
    cudaFuncSetAttribute(gemm3_kernel<false>,
                         cudaFuncAttributeMaxDynamicSharedMemorySize, SMEM_BYTES);

    // pre-transpose weights (once per graph replay, ~50us amortized)
    transpose_kernel<<<dim3(VV / 32, HH / 32), 256>>>(pwtout, W_out, VV, HH);
    transpose_kernel<<<dim3(G4 / 32, HH / 32), 256>>>(pwtg, W_ih, G4, HH);
    transpose_kernel<<<dim3(G4 / 32, HH / 32), 256>>>(
        pwtg + (size_t)HH * G4, W_hh, G4, HH);

    init_kernel<<<(BB * HH + 255) / 256, 256>>>(hidden);

    for (int t = 0; t < TT; t++) {
        // gates: split-K over 8 chunks of K=256 from [W_ih|W_hh]^T
        gemm3_kernel<true><<<dim3(G4 / BN, SPLITK), THR, SMEM_BYTES>>>(
            embedding, pwtg, nullptr, pgp, G4, KC_GATES);

        cell_kernel<<<(BB * HH / 4 + 255) / 256, 256>>>(b_ih, b_hh);

        // logits: h @ W_out^T + b_out  (K=1024)
        gemm3_kernel<false><<<dim3(VV / BN, 1), THR, SMEM_BYTES>>>(
            embedding, pwtout, b_out, plog, VV, HH);

        softmax_kernel<<<BB, 1024>>>(out, t);
    }
}